// round 2
// baseline (speedup 1.0000x reference)
#include <cuda_runtime.h>
#include <cstdint>

#define N_VEC   8192
#define K_CODES 16384
#define D_DIM   256
#define TM      128
#define TK      128
#define DC      16
#define NSPLIT  8
#define KSPAN   (K_CODES / NSPLIT)   // 2048

// Scratch (device globals — no allocation)
__device__ unsigned long long g_best[N_VEC];
__device__ float              g_sz[N_VEC];
__device__ double             g_loss_part[32];

// ---------------------------------------------------------------------------
// Kernel 0: init scratch
// ---------------------------------------------------------------------------
__global__ void vq_init_kernel() {
    int i = blockIdx.x * blockDim.x + threadIdx.x;
    if (i < N_VEC) g_best[i] = 0xFFFFFFFFFFFFFFFFULL;
    if (i < 32)    g_loss_part[i] = 0.0;
}

// ---------------------------------------------------------------------------
// Kernel 1: sz[n] = ||z_n||^2  (z is NCHW; row n = (b, h, w), d strided 1024)
// ---------------------------------------------------------------------------
__global__ void vq_sz_kernel(const float* __restrict__ z) {
    int n  = blockIdx.x * blockDim.x + threadIdx.x;
    int b  = n >> 10;
    int hw = n & 1023;
    const float* zp = z + (size_t)b * (D_DIM * 1024) + hw;
    float s = 0.f;
#pragma unroll 8
    for (int d = 0; d < D_DIM; d++) {
        float v = zp[(size_t)d * 1024];
        s = fmaf(v, v, s);
    }
    g_sz[n] = s;
}

// ---------------------------------------------------------------------------
// Kernel 2: fused fp32 GEMM + argmin, using packed fma.rn.f32x2 (FFMA2).
// Per-lane rounding of f32x2 is IEEE rn, identical to scalar FFMA, and the
// accumulation order per output element is unchanged vs the scalar kernel,
// so dval keys are bitwise identical.
// z values are stored DUPLICATED in smem so the (z,z) A-operand pairs load
// directly as 64-bit lanes; e pairs (e[2c],e[2c+1]) are naturally contiguous.
// ---------------------------------------------------------------------------
__global__ __launch_bounds__(256, 2)
void vq_gemm_kernel(const float* __restrict__ z, const float* __restrict__ emb) {
    __shared__ __align__(16) float zdup[DC][2 * TM];   // 16 KB, z duplicated
    __shared__ __align__(16) float es  [DC][TK + 4];   // 8.25 KB
    __shared__ unsigned long long sbest[TM];

    const int n0  = blockIdx.x * TM;        // 128-aligned -> single b per tile
    const int b   = n0 >> 10;
    const int hw0 = n0 & 1023;
    const int tid = threadIdx.x;
    const int tx  = tid & 15;
    const int ty  = tid >> 4;

    unsigned long long best[8];
#pragma unroll
    for (int r = 0; r < 8; r++) best[r] = 0xFFFFFFFFFFFFFFFFULL;

    float szr[8];
#pragma unroll
    for (int r = 0; r < 8; r++) szr[r] = g_sz[n0 + ty * 8 + r];

    const int kstart = blockIdx.y * KSPAN;

    for (int kb = 0; kb < KSPAN; kb += TK) {
        const int kbase = kstart + kb;

        // packed accumulators: acc2[r][c2] holds cols (2c2, 2c2+1) of row r
        unsigned long long acc2[8][4];
#pragma unroll
        for (int r = 0; r < 8; r++)
#pragma unroll
            for (int c = 0; c < 4; c++) acc2[r][c] = 0ULL;

        for (int db = 0; db < D_DIM; db += DC) {
            __syncthreads();   // protect smem from previous chunk's readers
            // load zdup[d][2*nn] = zdup[d][2*nn+1] = z value (coalesced over nn)
#pragma unroll
            for (int j = 0; j < 8; j++) {
                int i  = tid + 256 * j;
                int d  = i >> 7;
                int nn = i & 127;
                float v = z[(size_t)b * 262144 + (size_t)(db + d) * 1024 + hw0 + nn];
                *reinterpret_cast<float2*>(&zdup[d][2 * nn]) = make_float2(v, v);
            }
            // load es[d][kl]: emb[kbase+kl][db+d], float4 along d, transpose
#pragma unroll
            for (int j = 0; j < 2; j++) {
                int kl = (tid >> 2) + j * 64;
                int d4 = (tid & 3) * 4;
                float4 v = *reinterpret_cast<const float4*>(
                    &emb[(size_t)(kbase + kl) * D_DIM + db + d4]);
                es[d4 + 0][kl] = v.x;
                es[d4 + 1][kl] = v.y;
                es[d4 + 2][kl] = v.z;
                es[d4 + 3][kl] = v.w;
            }
            __syncthreads();

#pragma unroll
            for (int d = 0; d < DC; d++) {
                unsigned long long zd[8];   // (z,z) pairs, one per row
                unsigned long long ep[4];   // (e[2c],e[2c+1]) pairs
#pragma unroll
                for (int q = 0; q < 4; q++) {
                    ulonglong2 t = *reinterpret_cast<const ulonglong2*>(
                        &zdup[d][ty * 16 + 4 * q]);
                    zd[2 * q]     = t.x;
                    zd[2 * q + 1] = t.y;
                }
#pragma unroll
                for (int q = 0; q < 2; q++) {
                    ulonglong2 t = *reinterpret_cast<const ulonglong2*>(
                        &es[d][tx * 8 + 4 * q]);
                    ep[2 * q]     = t.x;
                    ep[2 * q + 1] = t.y;
                }
#pragma unroll
                for (int r = 0; r < 8; r++)
#pragma unroll
                    for (int c = 0; c < 4; c++)
                        asm("fma.rn.f32x2 %0, %1, %2, %0;"
                            : "+l"(acc2[r][c])
                            : "l"(zd[r]), "l"(ep[c]));
            }
        }

        // fold this k-tile into per-thread best (same scalar ops as before ->
        // bitwise-identical dval keys)
#pragma unroll
        for (int r = 0; r < 8; r++) {
#pragma unroll
            for (int c = 0; c < 4; c++) {
                unsigned long long v = acc2[r][c];
                float lo = __uint_as_float((unsigned int)(v & 0xFFFFFFFFu));
                float hi = __uint_as_float((unsigned int)(v >> 32));

                float dlo = __fsub_rn(szr[r], __fmul_rn(2.0f, lo));
                unsigned long long keylo =
                    ((unsigned long long)__float_as_uint(dlo) << 32) |
                    (unsigned int)(kbase + tx * 8 + 2 * c);
                if (keylo < best[r]) best[r] = keylo;

                float dhi = __fsub_rn(szr[r], __fmul_rn(2.0f, hi));
                unsigned long long keyhi =
                    ((unsigned long long)__float_as_uint(dhi) << 32) |
                    (unsigned int)(kbase + tx * 8 + 2 * c + 1);
                if (keyhi < best[r]) best[r] = keyhi;
            }
        }
    }

    // block-level reduction, then merge k-splits globally
    __syncthreads();
    if (tid < TM) sbest[tid] = 0xFFFFFFFFFFFFFFFFULL;
    __syncthreads();
#pragma unroll
    for (int r = 0; r < 8; r++)
        atomicMin(&sbest[ty * 8 + r], best[r]);
    __syncthreads();
    if (tid < TM)
        atomicMin(&g_best[n0 + tid], sbest[tid]);
}

// ---------------------------------------------------------------------------
// Kernel 3: gather emb[idx], straight-through output, idx output, partial loss
// ---------------------------------------------------------------------------
__global__ void vq_finalize_kernel(const float* __restrict__ z,
                                   const float* __restrict__ emb,
                                   float* __restrict__ out, int out_size) {
    __shared__ double sred[256];
    int n  = blockIdx.x * 256 + threadIdx.x;
    int b  = n >> 10;
    int hw = n & 1023;

    unsigned long long key = g_best[n];
    int k = (int)(unsigned int)(key & 0xFFFFFFFFu);

    const float* e  = emb + (size_t)k * D_DIM;
    const float* zp = z   + (size_t)b * 262144 + hw;
    float*       op = out + (size_t)b * 262144 + hw;

    double lsum = 0.0;
#pragma unroll 4
    for (int d = 0; d < D_DIM; d++) {
        float zv   = zp[(size_t)d * 1024];
        float ev   = e[d];
        float diff = __fsub_rn(ev, zv);          // fl(z_q - z)
        float q    = __fadd_rn(zv, diff);        // fl(z + fl(z_q - z)) = ST value
        op[(size_t)d * 1024] = q;
        lsum += (double)diff * (double)diff;
    }

    int idx_pos = 2097152 + 1 + n;
    if (idx_pos < out_size) out[idx_pos] = (float)k;

    sred[threadIdx.x] = lsum;
    __syncthreads();
    for (int s = 128; s > 0; s >>= 1) {
        if (threadIdx.x < s) sred[threadIdx.x] += sred[threadIdx.x + s];
        __syncthreads();
    }
    if (threadIdx.x == 0) g_loss_part[blockIdx.x] = sred[0];
}

// ---------------------------------------------------------------------------
// Kernel 4: final loss = (1 + BETA) * mean(diff^2), deterministic order
// ---------------------------------------------------------------------------
__global__ void vq_loss_kernel(float* __restrict__ out, int out_size) {
    if (threadIdx.x == 0 && blockIdx.x == 0) {
        double s = 0.0;
        for (int i = 0; i < 32; i++) s += g_loss_part[i];
        double mean = s / 2097152.0;
        if (2097152 < out_size) out[2097152] = (float)(mean * 1.25);
    }
}

// ---------------------------------------------------------------------------
extern "C" void kernel_launch(void* const* d_in, const int* in_sizes, int n_in,
                              void* d_out, int out_size) {
    const float* z   = (const float*)d_in[0];   // [8,256,32,32]
    const float* emb = (const float*)d_in[1];   // [16384,256]
    float* out = (float*)d_out;

    vq_init_kernel<<<32, 256>>>();
    vq_sz_kernel<<<32, 256>>>(z);
    dim3 grid(N_VEC / TM, NSPLIT);
    vq_gemm_kernel<<<grid, 256>>>(z, emb);
    vq_finalize_kernel<<<32, 256>>>(z, emb, out, out_size);
    vq_loss_kernel<<<1, 32>>>(out, out_size);
}

// round 4
// speedup vs baseline: 2.3802x; 2.3802x over previous
#include <cuda_runtime.h>
#include <cuda_bf16.h>
#include <cstdint>

#define N_VEC    8192
#define K_CODES  16384
#define D_DIM    256
#define CAND_MAX (1 << 20)
#define MARGIN_D1 6e-4f

// ------------------------- device scratch (globals) -------------------------
__device__ __nv_bfloat16      g_abf[N_VEC * D_DIM];     // z rows, bf16(rn)
__device__ __nv_bfloat16      g_bbf[K_CODES * D_DIM];   // emb rows, bf16(rn)
__device__ float              g_zf [N_VEC * D_DIM];     // z rows, fp32 packed
__device__ float              g_sz [N_VEC];
__device__ unsigned int       g_rowmin[N_VEC];          // bits of min d1 (>0)
__device__ unsigned long long g_best[N_VEC];            // (bits(d)<<32)|k
__device__ unsigned int       g_cand[CAND_MAX];         // (n<<14)|k
__device__ unsigned int       g_ncand;
__device__ double             g_loss_part[256];

// ------------------------------ PTX helpers --------------------------------
__device__ __forceinline__ uint32_t smem_u32(const void* p) {
    uint32_t a;
    asm("{ .reg .u64 t; cvta.to.shared.u64 t, %1; cvt.u32.u64 %0, t; }"
        : "=r"(a) : "l"(p));
    return a;
}
__device__ __forceinline__ void ldm_x4(uint32_t* r, uint32_t addr) {
    asm volatile("ldmatrix.sync.aligned.m8n8.x4.shared.b16 {%0,%1,%2,%3}, [%4];"
                 : "=r"(r[0]), "=r"(r[1]), "=r"(r[2]), "=r"(r[3]) : "r"(addr));
}
__device__ __forceinline__ void mma_bf16(float* c, const uint32_t* a,
                                         uint32_t b0, uint32_t b1) {
    asm volatile(
        "mma.sync.aligned.m16n8k16.row.col.f32.bf16.bf16.f32 "
        "{%0,%1,%2,%3}, {%4,%5,%6,%7}, {%8,%9}, {%0,%1,%2,%3};"
        : "+f"(c[0]), "+f"(c[1]), "+f"(c[2]), "+f"(c[3])
        : "r"(a[0]), "r"(a[1]), "r"(a[2]), "r"(a[3]), "r"(b0), "r"(b1));
}

// ---------------------------------------------------------------------------
// Kernel: init scratch
// ---------------------------------------------------------------------------
__global__ void vq_init_kernel() {
    int i = blockIdx.x * blockDim.x + threadIdx.x;
    if (i < N_VEC) {
        g_best[i]   = 0xFFFFFFFFFFFFFFFFULL;
        g_rowmin[i] = 0x7F800000u;              // +inf
    }
    if (i < 256) g_loss_part[i] = 0.0;
    if (i == 0)  g_ncand = 0;
}

// ---------------------------------------------------------------------------
// Kernel: pack z -> zf (fp32 row-major), abf (bf16), sz (sequential chain,
// identical order to the R1 kernel that verified rel_err 0.0)
// ---------------------------------------------------------------------------
__global__ void vq_pack_z_kernel(const float* __restrict__ z) {
    int n  = blockIdx.x * blockDim.x + threadIdx.x;
    int b  = n >> 10;
    int hw = n & 1023;
    const float* zp = z + (size_t)b * 262144 + hw;
    float s = 0.f;
#pragma unroll 8
    for (int d = 0; d < D_DIM; d++) {
        float v = zp[(size_t)d * 1024];
        g_zf [n * D_DIM + d] = v;
        g_abf[n * D_DIM + d] = __float2bfloat16_rn(v);
        s = fmaf(v, v, s);
    }
    g_sz[n] = s;
}

__global__ void vq_pack_e_kernel(const float* __restrict__ emb) {
    int i0 = blockIdx.x * 1024 + threadIdx.x;
#pragma unroll
    for (int j = 0; j < 4; j++) {
        int i = i0 + j * 256;
        g_bbf[i] = __float2bfloat16_rn(emb[i]);
    }
}

// ---------------------------------------------------------------------------
// bf16 HMMA GEMM tile: C[128 z-rows, 128 codes] = z_hi · e_hiᵀ over K=256.
// Block 128x128, BK=32, 8 warps (4m x 2n), warp tile 32x64.
// PASS 1: per-row atomicMin of d1 = fl(1 - 2*acc)
// PASS 2: emit candidates with d1 <= rowmin + margin (acc bitwise == pass 1)
// ---------------------------------------------------------------------------
template <int PASS>
__global__ __launch_bounds__(256)
void vq_mma_kernel() {
    __shared__ __align__(16) __nv_bfloat16 sA[128][40];  // 32 + 8 pad (80 B)
    __shared__ __align__(16) __nv_bfloat16 sB[128][40];

    const int tid  = threadIdx.x;
    const int lane = tid & 31;
    const int wid  = tid >> 5;
    const int wm   = wid >> 1;               // 0..3
    const int wn   = wid & 1;                // 0..1
    const int n0   = blockIdx.x * 128;       // z-row base
    const int k0   = blockIdx.y * 128;       // code base

    float acc[2][8][4];
#pragma unroll
    for (int mi = 0; mi < 2; mi++)
#pragma unroll
        for (int ni = 0; ni < 8; ni++)
#pragma unroll
            for (int r = 0; r < 4; r++) acc[mi][ni][r] = 0.f;

    const int lrow = tid >> 2;        // 0..63  (two rows per thread per tile)
    const int lq   = (tid & 3) * 8;   // bf16 col of 16-byte chunk

    for (int kc = 0; kc < 8; kc++) {
        const int kb = kc * 32;
        __syncthreads();
#pragma unroll
        for (int j = 0; j < 2; j++) {
            int row = lrow + j * 64;
            *reinterpret_cast<uint4*>(&sA[row][lq]) =
                *reinterpret_cast<const uint4*>(
                    &g_abf[(size_t)(n0 + row) * D_DIM + kb + lq]);
            *reinterpret_cast<uint4*>(&sB[row][lq]) =
                *reinterpret_cast<const uint4*>(
                    &g_bbf[(size_t)(k0 + row) * D_DIM + kb + lq]);
        }
        __syncthreads();

#pragma unroll
        for (int ks = 0; ks < 2; ks++) {
            uint32_t a[2][4];
#pragma unroll
            for (int mi = 0; mi < 2; mi++) {
                int r = wm * 32 + mi * 16 + (lane & 15);
                int c = ks * 16 + (lane >> 4) * 8;
                ldm_x4(a[mi], smem_u32(&sA[r][c]));
            }
            uint32_t b[4][4];
#pragma unroll
            for (int g = 0; g < 4; g++) {
                int r = wn * 64 + g * 16 + (lane & 15);
                int c = ks * 16 + (lane >> 4) * 8;
                ldm_x4(b[g], smem_u32(&sB[r][c]));
            }
#pragma unroll
            for (int mi = 0; mi < 2; mi++)
#pragma unroll
                for (int g = 0; g < 4; g++) {
                    mma_bf16(acc[mi][2 * g],     a[mi], b[g][0], b[g][2]);
                    mma_bf16(acc[mi][2 * g + 1], a[mi], b[g][1], b[g][3]);
                }
        }
    }

    // epilogue: thread holds rows n0 + wm*32 + mi*16 + ci*8 + lane/4,
    // cols k0 + wn*64 + ni*8 + (lane%4)*2 + r
    if (PASS == 1) {
#pragma unroll
        for (int mi = 0; mi < 2; mi++)
#pragma unroll
            for (int ci = 0; ci < 2; ci++) {
                float mn = 3.402823466e+38f;
#pragma unroll
                for (int ni = 0; ni < 8; ni++) {
                    float d0 = __fmaf_rn(-2.0f, acc[mi][ni][2 * ci],     1.0f);
                    float d1 = __fmaf_rn(-2.0f, acc[mi][ni][2 * ci + 1], 1.0f);
                    mn = fminf(mn, fminf(d0, d1));
                }
                mn = fminf(mn, __shfl_xor_sync(0xFFFFFFFFu, mn, 1));
                mn = fminf(mn, __shfl_xor_sync(0xFFFFFFFFu, mn, 2));
                if ((lane & 3) == 0) {
                    int n = n0 + wm * 32 + mi * 16 + ci * 8 + (lane >> 2);
                    atomicMin(&g_rowmin[n], __float_as_uint(mn));
                }
            }
    } else {
#pragma unroll
        for (int mi = 0; mi < 2; mi++)
#pragma unroll
            for (int ci = 0; ci < 2; ci++) {
                int n = n0 + wm * 32 + mi * 16 + ci * 8 + (lane >> 2);
                float thr = __uint_as_float(g_rowmin[n]) + MARGIN_D1;
#pragma unroll
                for (int ni = 0; ni < 8; ni++)
#pragma unroll
                    for (int r = 0; r < 2; r++) {
                        float dv = __fmaf_rn(-2.0f, acc[mi][ni][2 * ci + r], 1.0f);
                        if (dv <= thr) {
                            unsigned int pos = atomicAdd(&g_ncand, 1u);
                            if (pos < CAND_MAX) {
                                int k = k0 + wn * 64 + ni * 8 + (lane & 3) * 2 + r;
                                g_cand[pos] = ((unsigned int)n << 14) |
                                              (unsigned int)k;
                            }
                        }
                    }
            }
    }
}

// ---------------------------------------------------------------------------
// Kernel: exact fp32 rescore of candidates — sequential FMA chain identical
// to the verified R1 kernel, then lexicographic (bits(d), k) atomicMin.
// ---------------------------------------------------------------------------
__global__ void vq_rescore_kernel(const float* __restrict__ emb) {
    unsigned int total = g_ncand;
    if (total > CAND_MAX) total = CAND_MAX;
    for (unsigned int i = blockIdx.x * blockDim.x + threadIdx.x;
         i < total; i += gridDim.x * blockDim.x) {
        unsigned int c = g_cand[i];
        int n = c >> 14;
        int k = c & 16383;
        const float* zr = g_zf + (size_t)n * D_DIM;
        const float* er = emb  + (size_t)k * D_DIM;
        float acc = 0.f;
#pragma unroll 8
        for (int d = 0; d < D_DIM; d++)
            acc = fmaf(zr[d], er[d], acc);
        float dval = __fsub_rn(g_sz[n], __fmul_rn(2.0f, acc));
        unsigned long long key =
            ((unsigned long long)__float_as_uint(dval) << 32) | (unsigned int)k;
        atomicMin(&g_best[n], key);
    }
}

// ---------------------------------------------------------------------------
// Kernel: gather emb[idx], straight-through output, idx output, loss partials
// 256 blocks: (ngroup 0..31) x (dchunk 0..7)
// ---------------------------------------------------------------------------
__global__ void vq_finalize_kernel(const float* __restrict__ z,
                                   const float* __restrict__ emb,
                                   float* __restrict__ out, int out_size) {
    __shared__ double sred[256];
    int ng = blockIdx.x >> 3;
    int dc = blockIdx.x & 7;
    int n  = ng * 256 + threadIdx.x;
    int b  = n >> 10;
    int hw = n & 1023;

    int k = (int)(unsigned int)(g_best[n] & 0xFFFFFFFFu);

    const float* e  = emb + (size_t)k * D_DIM;
    const float* zp = z   + (size_t)b * 262144 + hw;
    float*       op = out + (size_t)b * 262144 + hw;

    double lsum = 0.0;
#pragma unroll 8
    for (int d = dc * 32; d < dc * 32 + 32; d++) {
        float zv   = zp[(size_t)d * 1024];
        float ev   = e[d];
        float diff = __fsub_rn(ev, zv);          // fl(z_q - z)
        float q    = __fadd_rn(zv, diff);        // fl(z + fl(z_q - z))
        op[(size_t)d * 1024] = q;
        lsum += (double)diff * (double)diff;
    }

    if (dc == 0) {
        int idx_pos = 2097152 + 1 + n;
        if (idx_pos < out_size) out[idx_pos] = (float)k;
    }

    sred[threadIdx.x] = lsum;
    __syncthreads();
    for (int s = 128; s > 0; s >>= 1) {
        if (threadIdx.x < s) sred[threadIdx.x] += sred[threadIdx.x + s];
        __syncthreads();
    }
    if (threadIdx.x == 0) g_loss_part[blockIdx.x] = sred[0];
}

__global__ void vq_loss_kernel(float* __restrict__ out, int out_size) {
    if (threadIdx.x == 0 && blockIdx.x == 0) {
        double s = 0.0;
        for (int i = 0; i < 256; i++) s += g_loss_part[i];
        double mean = s / 2097152.0;
        if (2097152 < out_size) out[2097152] = (float)(mean * 1.25);
    }
}

// ---------------------------------------------------------------------------
extern "C" void kernel_launch(void* const* d_in, const int* in_sizes, int n_in,
                              void* d_out, int out_size) {
    const float* z   = (const float*)d_in[0];   // [8,256,32,32]
    const float* emb = (const float*)d_in[1];   // [16384,256]
    float* out = (float*)d_out;

    vq_init_kernel<<<32, 256>>>();
    vq_pack_z_kernel<<<32, 256>>>(z);
    vq_pack_e_kernel<<<4096, 256>>>(emb);

    dim3 grid(N_VEC / 128, K_CODES / 128);     // 64 x 128
    vq_mma_kernel<1><<<grid, 256>>>();
    vq_mma_kernel<2><<<grid, 256>>>();

    vq_rescore_kernel<<<512, 256>>>(emb);
    vq_finalize_kernel<<<256, 256>>>(z, emb, out, out_size);
    vq_loss_kernel<<<1, 32>>>(out, out_size);
}